// round 3
// baseline (speedup 1.0000x reference)
#include <cuda_runtime.h>
#include <math.h>

#define N_SEQ 4096
#define N_HEADS 16
#define DIM_HEAD 64
#define DIM 1024

// Scratch (device globals — no allocation allowed)
__device__ float g_qT[N_HEADS * DIM_HEAD * N_SEQ];   // [h][d][n], pre-scaled by 0.125*log2e
__device__ float g_kT[N_HEADS * DIM_HEAD * N_SEQ];   // [h][d][n]
__device__ float g_attnT[DIM * N_SEQ];               // [i][n]  (transposed attention output)
__device__ float g_wT[DIM * DIM];                    // [i][j]  (w_out transposed)
__device__ float g_cos[N_SEQ * 32];
__device__ float g_sin[N_SEQ * 32];

// ---------------------------------------------------------------------------
// Kernel 0: RoPE tables. inv_freq correctly rounded via double exp/log; angle
// rounded to fp32 exactly like the reference (fl(n * inv_freq32)); sincos in
// double of that fp32 angle -> matches jax cos/sin to ~1 ulp.
// ---------------------------------------------------------------------------
__global__ void rope_table_kernel() {
    int idx = blockIdx.x * blockDim.x + threadIdx.x;
    if (idx >= N_SEQ * 32) return;
    int n = idx >> 5;
    int l = idx & 31;
    float invf = (float)exp(-((double)l / 32.0) * log(10000.0));
    float ang = (float)n * invf;          // fp32 rounding, like reference
    double s, c;
    sincos((double)ang, &s, &c);
    g_cos[idx] = (float)c;
    g_sin[idx] = (float)s;
}

// ---------------------------------------------------------------------------
// Kernel 1: preprocess q/k: RoPE + l2-norm + qk_scale (+ softmax scale folded
// into q). Writes head-major transposed layout [h][d][n] via smem tile.
// grid: (64 n-tiles, 16 heads, 2 tensors), 256 threads (8 warps x 8 rows).
// ---------------------------------------------------------------------------
__global__ __launch_bounds__(256) void prep_kernel(
    const float* __restrict__ q, const float* __restrict__ k,
    const float* __restrict__ qk_scale)
{
    __shared__ float tile[64 * 65];
    int w = threadIdx.x >> 5;
    int lane = threadIdx.x & 31;
    int h = blockIdx.y;
    const float* src = (blockIdx.z == 0) ? q : k;
    float* dstT      = (blockIdx.z == 0) ? g_qT : g_kT;
    // fold (1/sqrt(D)) * log2(e) into q so scores are in log2 units
    float fold = (blockIdx.z == 0) ? (0.125f * 1.4426950408889634f) : 1.0f;

    float2 sc = ((const float2*)qk_scale)[lane];

    for (int rr = 0; rr < 8; rr++) {
        int nl = w * 8 + rr;
        int n = blockIdx.x * 64 + nl;
        const float2* row = (const float2*)(src + (size_t)n * DIM + h * DIM_HEAD);
        float2 x = row[lane];
        float c = g_cos[n * 32 + lane];
        float s = g_sin[n * 32 + lane];
        float orr = x.x * c - x.y * s;
        float oii = x.x * s + x.y * c;
        float sq = orr * orr + oii * oii;
        #pragma unroll
        for (int m = 16; m; m >>= 1) sq += __shfl_xor_sync(0xffffffffu, sq, m);
        float inv = 1.0f / fmaxf(sqrtf(sq), 1e-12f);
        float f = inv * fold;
        tile[(2 * lane) * 65 + nl]     = orr * f * sc.x;
        tile[(2 * lane + 1) * 65 + nl] = oii * f * sc.y;
    }
    __syncthreads();
    #pragma unroll
    for (int it = 0; it < 16; it++) {
        int idx = threadIdx.x + it * 256;
        int d = idx >> 6, nl = idx & 63;
        dstT[(h * DIM_HEAD + d) * N_SEQ + blockIdx.x * 64 + nl] = tile[d * 65 + nl];
    }
}

// ---------------------------------------------------------------------------
// Kernel 2: flash attention. 64 queries x 64 keys tiles. 256 threads as 16x16,
// 4x4 register fragments. Q/K smem layout [d][n] -> contiguous float4 frag
// loads. PV uses shfl broadcast of exp'd score fragments (no P smem buffer).
// smem = 3 * 16KB = 48KB (static limit, no opt-in).
// ---------------------------------------------------------------------------
__global__ __launch_bounds__(256) void attn_kernel(const float* __restrict__ v_in)
{
    __shared__ float Qs[64 * 64];   // [d][m]
    __shared__ float Ks[64 * 64];   // [d][kk]
    __shared__ float Vs[64 * 64];   // [kk][d]

    int h = blockIdx.y;
    int m0 = blockIdx.x * 64;
    int tid = threadIdx.x;
    int tx = tid & 15, ty = tid >> 4;
    int lane = tid & 31;

    #pragma unroll
    for (int it = 0; it < 16; it++) {
        int idx = tid + it * 256;
        int d = idx >> 6, ml = idx & 63;
        Qs[idx] = g_qT[(h * DIM_HEAD + d) * N_SEQ + m0 + ml];
    }

    float o[4][4];
    float mrow[4], lrow[4];
    #pragma unroll
    for (int i = 0; i < 4; i++) {
        mrow[i] = -INFINITY; lrow[i] = 0.0f;
        #pragma unroll
        for (int j = 0; j < 4; j++) o[i][j] = 0.0f;
    }

    for (int kt = 0; kt < 64; kt++) {
        int k0 = kt * 64;
        __syncthreads();   // protect Ks/Vs reuse (and initial Qs writes)
        #pragma unroll
        for (int it = 0; it < 16; it++) {
            int idx = tid + it * 256;
            int d = idx >> 6, kl = idx & 63;
            Ks[idx] = g_kT[(h * DIM_HEAD + d) * N_SEQ + k0 + kl];
        }
        #pragma unroll
        for (int it = 0; it < 16; it++) {
            int idx = tid + it * 256;
            int kk = idx >> 6, d = idx & 63;
            Vs[idx] = v_in[(size_t)(k0 + kk) * DIM + h * DIM_HEAD + d];
        }
        __syncthreads();

        // S = Q K^T  (log2 units; scale folded into q)
        float s[4][4];
        #pragma unroll
        for (int i = 0; i < 4; i++)
            #pragma unroll
            for (int j = 0; j < 4; j++) s[i][j] = 0.0f;

        #pragma unroll 8
        for (int d = 0; d < 64; d++) {
            float4 q4 = *(const float4*)&Qs[d * 64 + ty * 4];
            float4 k4 = *(const float4*)&Ks[d * 64 + tx * 4];
            float qa[4] = {q4.x, q4.y, q4.z, q4.w};
            float ka[4] = {k4.x, k4.y, k4.z, k4.w};
            #pragma unroll
            for (int i = 0; i < 4; i++)
                #pragma unroll
                for (int j = 0; j < 4; j++) s[i][j] = fmaf(qa[i], ka[j], s[i][j]);
        }

        // online softmax update
        #pragma unroll
        for (int i = 0; i < 4; i++) {
            float rmax = fmaxf(fmaxf(s[i][0], s[i][1]), fmaxf(s[i][2], s[i][3]));
            #pragma unroll
            for (int m = 1; m < 16; m <<= 1)
                rmax = fmaxf(rmax, __shfl_xor_sync(0xffffffffu, rmax, m));
            float mnew = fmaxf(mrow[i], rmax);
            float alpha = exp2f(mrow[i] - mnew);
            mrow[i] = mnew;
            float rs = 0.0f;
            #pragma unroll
            for (int j = 0; j < 4; j++) {
                s[i][j] = exp2f(s[i][j] - mnew);
                rs += s[i][j];
            }
            #pragma unroll
            for (int m = 1; m < 16; m <<= 1)
                rs += __shfl_xor_sync(0xffffffffu, rs, m);
            lrow[i] = lrow[i] * alpha + rs;
            #pragma unroll
            for (int j = 0; j < 4; j++) o[i][j] *= alpha;
        }

        // O += P V : shfl-broadcast p fragments (source lane owns key kk)
        for (int kk4 = 0; kk4 < 16; kk4++) {
            int src = (lane & 16) | kk4;
            #pragma unroll
            for (int u = 0; u < 4; u++) {
                float4 v4 = *(const float4*)&Vs[(kk4 * 4 + u) * 64 + tx * 4];
                float pb0 = __shfl_sync(0xffffffffu, s[0][u], src);
                float pb1 = __shfl_sync(0xffffffffu, s[1][u], src);
                float pb2 = __shfl_sync(0xffffffffu, s[2][u], src);
                float pb3 = __shfl_sync(0xffffffffu, s[3][u], src);
                o[0][0] = fmaf(pb0, v4.x, o[0][0]); o[0][1] = fmaf(pb0, v4.y, o[0][1]);
                o[0][2] = fmaf(pb0, v4.z, o[0][2]); o[0][3] = fmaf(pb0, v4.w, o[0][3]);
                o[1][0] = fmaf(pb1, v4.x, o[1][0]); o[1][1] = fmaf(pb1, v4.y, o[1][1]);
                o[1][2] = fmaf(pb1, v4.z, o[1][2]); o[1][3] = fmaf(pb1, v4.w, o[1][3]);
                o[2][0] = fmaf(pb2, v4.x, o[2][0]); o[2][1] = fmaf(pb2, v4.y, o[2][1]);
                o[2][2] = fmaf(pb2, v4.z, o[2][2]); o[2][3] = fmaf(pb2, v4.w, o[2][3]);
                o[3][0] = fmaf(pb3, v4.x, o[3][0]); o[3][1] = fmaf(pb3, v4.y, o[3][1]);
                o[3][2] = fmaf(pb3, v4.z, o[3][2]); o[3][3] = fmaf(pb3, v4.w, o[3][3]);
            }
        }
    }

    // epilogue: normalize and write transposed [i][n] via smem staging
    #pragma unroll
    for (int i = 0; i < 4; i++) {
        float invl = 1.0f / lrow[i];
        #pragma unroll
        for (int j = 0; j < 4; j++) o[i][j] *= invl;
    }
    __syncthreads();
    #pragma unroll
    for (int i = 0; i < 4; i++)
        #pragma unroll
        for (int j = 0; j < 4; j++)
            Qs[(tx * 4 + j) * 64 + ty * 4 + i] = o[i][j];
    __syncthreads();
    #pragma unroll
    for (int it = 0; it < 16; it++) {
        int idx = tid + it * 256;
        int d = idx >> 6, ml = idx & 63;
        g_attnT[(h * DIM_HEAD + d) * N_SEQ + m0 + ml] = Qs[idx];
    }
}

// ---------------------------------------------------------------------------
// Kernel 3: transpose w_out [j][i] -> g_wT [i][j]
// ---------------------------------------------------------------------------
__global__ __launch_bounds__(256) void transpose_w_kernel(const float* __restrict__ w)
{
    __shared__ float t[64 * 65];
    int j0 = blockIdx.x * 64, i0 = blockIdx.y * 64;
    #pragma unroll
    for (int it = 0; it < 16; it++) {
        int idx = threadIdx.x + it * 256;
        int jl = idx >> 6, il = idx & 63;
        t[jl * 65 + il] = w[(j0 + jl) * DIM + i0 + il];
    }
    __syncthreads();
    #pragma unroll
    for (int it = 0; it < 16; it++) {
        int idx = threadIdx.x + it * 256;
        int il = idx >> 6, jl = idx & 63;
        g_wT[(i0 + il) * DIM + j0 + jl] = t[jl * 65 + il];
    }
}

// ---------------------------------------------------------------------------
// Kernel 4: projection GEMM: out[n][j] = sum_i attn[n][i] * w[j][i] + b[j]
// Both operands K-outer in smem, 64x64 tiles, 4x4 fragments, float4 loads.
// ---------------------------------------------------------------------------
__global__ __launch_bounds__(256) void proj_kernel(
    const float* __restrict__ b_out, float* __restrict__ out)
{
    __shared__ float As[64 * 64];  // [kk][m]
    __shared__ float Ws[64 * 64];  // [kk][j]
    int m0 = blockIdx.x * 64, j0 = blockIdx.y * 64;
    int tid = threadIdx.x;
    int tx = tid & 15, ty = tid >> 4;

    float acc[4][4];
    #pragma unroll
    for (int i = 0; i < 4; i++)
        #pragma unroll
        for (int j = 0; j < 4; j++) acc[i][j] = 0.0f;

    for (int k0 = 0; k0 < DIM; k0 += 64) {
        __syncthreads();
        #pragma unroll
        for (int it = 0; it < 16; it++) {
            int idx = tid + it * 256;
            int kk = idx >> 6, ml = idx & 63;
            As[idx] = g_attnT[(k0 + kk) * N_SEQ + m0 + ml];
            Ws[idx] = g_wT[(k0 + kk) * DIM + j0 + ml];
        }
        __syncthreads();
        #pragma unroll 8
        for (int kk = 0; kk < 64; kk++) {
            float4 a4 = *(const float4*)&As[kk * 64 + ty * 4];
            float4 w4 = *(const float4*)&Ws[kk * 64 + tx * 4];
            float aa[4] = {a4.x, a4.y, a4.z, a4.w};
            float ww[4] = {w4.x, w4.y, w4.z, w4.w};
            #pragma unroll
            for (int i = 0; i < 4; i++)
                #pragma unroll
                for (int j = 0; j < 4; j++) acc[i][j] = fmaf(aa[i], ww[j], acc[i][j]);
        }
    }

    float4 bb = *(const float4*)&b_out[j0 + tx * 4];
    #pragma unroll
    for (int i = 0; i < 4; i++) {
        float4 r;
        r.x = acc[i][0] + bb.x;
        r.y = acc[i][1] + bb.y;
        r.z = acc[i][2] + bb.z;
        r.w = acc[i][3] + bb.w;
        *(float4*)&out[(size_t)(m0 + ty * 4 + i) * DIM + j0 + tx * 4] = r;
    }
}

// ---------------------------------------------------------------------------
extern "C" void kernel_launch(void* const* d_in, const int* in_sizes, int n_in,
                              void* d_out, int out_size)
{
    const float* q        = (const float*)d_in[0];
    const float* k        = (const float*)d_in[1];
    const float* v        = (const float*)d_in[2];
    const float* qk_scale = (const float*)d_in[3];
    const float* w_out    = (const float*)d_in[4];
    const float* b_out    = (const float*)d_in[5];
    float* out = (float*)d_out;

    rope_table_kernel<<<(N_SEQ * 32 + 255) / 256, 256>>>();
    prep_kernel<<<dim3(N_SEQ / 64, N_HEADS, 2), 256>>>(q, k, qk_scale);
    transpose_w_kernel<<<dim3(DIM / 64, DIM / 64), 256>>>(w_out);
    attn_kernel<<<dim3(N_SEQ / 64, N_HEADS), 256>>>(v);
    proj_kernel<<<dim3(N_SEQ / 64, DIM / 64), 256>>>(b_out, out);
}

// round 4
// speedup vs baseline: 1.0551x; 1.0551x over previous
#include <cuda_runtime.h>
#include <math.h>

#define N_SEQ 4096
#define N_HEADS 16
#define DIM_HEAD 64
#define DIM 1024

// Scratch (device globals — no allocation allowed)
__device__ float g_qT[N_HEADS * DIM_HEAD * N_SEQ];   // [h][d][n], pre-scaled by 0.125*log2e
__device__ float g_kT[N_HEADS * DIM_HEAD * N_SEQ];   // [h][d][n]
__device__ float g_attnT[DIM * N_SEQ];               // [i][n]  (transposed attention output)
__device__ float g_wT[DIM * DIM];                    // [i][j]  (w_out transposed)
__device__ float g_cos[N_SEQ * 32];
__device__ float g_sin[N_SEQ * 32];

// ---------------------------------------------------------------------------
// Kernel 0: RoPE tables. inv_freq correctly rounded via double exp/log; angle
// rounded to fp32 exactly like the reference (fl(n * inv_freq32)); sincos in
// double of that fp32 angle -> matches jax cos/sin to ~1 ulp.
// ---------------------------------------------------------------------------
__global__ void rope_table_kernel() {
    int idx = blockIdx.x * blockDim.x + threadIdx.x;
    if (idx >= N_SEQ * 32) return;
    int n = idx >> 5;
    int l = idx & 31;
    float invf = (float)exp(-((double)l / 32.0) * log(10000.0));
    float ang = (float)n * invf;          // fp32 rounding, like reference
    double s, c;
    sincos((double)ang, &s, &c);
    g_cos[idx] = (float)c;
    g_sin[idx] = (float)s;
}

// ---------------------------------------------------------------------------
// Kernel 1: preprocess q/k: RoPE + l2-norm + qk_scale (+ softmax scale folded
// into q). Writes head-major transposed layout [h][d][n] via smem tile.
// grid: (64 n-tiles, 16 heads, 2 tensors), 256 threads (8 warps x 8 rows).
// ---------------------------------------------------------------------------
__global__ __launch_bounds__(256) void prep_kernel(
    const float* __restrict__ q, const float* __restrict__ k,
    const float* __restrict__ qk_scale)
{
    __shared__ float tile[64 * 65];
    int w = threadIdx.x >> 5;
    int lane = threadIdx.x & 31;
    int h = blockIdx.y;
    const float* src = (blockIdx.z == 0) ? q : k;
    float* dstT      = (blockIdx.z == 0) ? g_qT : g_kT;
    // fold (1/sqrt(D)) * log2(e) into q so scores are in log2 units
    float fold = (blockIdx.z == 0) ? (0.125f * 1.4426950408889634f) : 1.0f;

    float2 sc = ((const float2*)qk_scale)[lane];

    for (int rr = 0; rr < 8; rr++) {
        int nl = w * 8 + rr;
        int n = blockIdx.x * 64 + nl;
        const float2* row = (const float2*)(src + (size_t)n * DIM + h * DIM_HEAD);
        float2 x = row[lane];
        float c = g_cos[n * 32 + lane];
        float s = g_sin[n * 32 + lane];
        float orr = x.x * c - x.y * s;
        float oii = x.x * s + x.y * c;
        float sq = orr * orr + oii * oii;
        #pragma unroll
        for (int m = 16; m; m >>= 1) sq += __shfl_xor_sync(0xffffffffu, sq, m);
        float inv = 1.0f / fmaxf(sqrtf(sq), 1e-12f);
        float f = inv * fold;
        tile[(2 * lane) * 65 + nl]     = orr * f * sc.x;
        tile[(2 * lane + 1) * 65 + nl] = oii * f * sc.y;
    }
    __syncthreads();
    #pragma unroll
    for (int it = 0; it < 16; it++) {
        int idx = threadIdx.x + it * 256;
        int d = idx >> 6, nl = idx & 63;
        dstT[(h * DIM_HEAD + d) * N_SEQ + blockIdx.x * 64 + nl] = tile[d * 65 + nl];
    }
}

// ---------------------------------------------------------------------------
// Kernel 2: flash attention. 64 queries x 64 keys tiles. 256 threads as 16x16,
// 4x4 register fragments. Q/K smem layout [d][n] -> contiguous float4 frag
// loads. PV uses shfl broadcast of exp'd score fragments (no P smem buffer).
// smem = 3 * 16KB = 48KB (static limit, no opt-in).
// ---------------------------------------------------------------------------
__global__ __launch_bounds__(256) void attn_kernel(const float* __restrict__ v_in)
{
    __shared__ float Qs[64 * 64];   // [d][m]
    __shared__ float Ks[64 * 64];   // [d][kk]
    __shared__ float Vs[64 * 64];   // [kk][d]

    int h = blockIdx.y;
    int m0 = blockIdx.x * 64;
    int tid = threadIdx.x;
    int tx = tid & 15, ty = tid >> 4;
    int lane = tid & 31;

    #pragma unroll
    for (int it = 0; it < 16; it++) {
        int idx = tid + it * 256;
        int d = idx >> 6, ml = idx & 63;
        Qs[idx] = g_qT[(h * DIM_HEAD + d) * N_SEQ + m0 + ml];
    }

    float o[4][4];
    float mrow[4], lrow[4];
    #pragma unroll
    for (int i = 0; i < 4; i++) {
        mrow[i] = -INFINITY; lrow[i] = 0.0f;
        #pragma unroll
        for (int j = 0; j < 4; j++) o[i][j] = 0.0f;
    }

    for (int kt = 0; kt < 64; kt++) {
        int k0 = kt * 64;
        __syncthreads();   // protect Ks/Vs reuse (and initial Qs writes)
        #pragma unroll
        for (int it = 0; it < 16; it++) {
            int idx = tid + it * 256;
            int d = idx >> 6, kl = idx & 63;
            Ks[idx] = g_kT[(h * DIM_HEAD + d) * N_SEQ + k0 + kl];
        }
        #pragma unroll
        for (int it = 0; it < 16; it++) {
            int idx = tid + it * 256;
            int kk = idx >> 6, d = idx & 63;
            Vs[idx] = v_in[(size_t)(k0 + kk) * DIM + h * DIM_HEAD + d];
        }
        __syncthreads();

        // S = Q K^T  (log2 units; scale folded into q)
        float s[4][4];
        #pragma unroll
        for (int i = 0; i < 4; i++)
            #pragma unroll
            for (int j = 0; j < 4; j++) s[i][j] = 0.0f;

        #pragma unroll 8
        for (int d = 0; d < 64; d++) {
            float4 q4 = *(const float4*)&Qs[d * 64 + ty * 4];
            float4 k4 = *(const float4*)&Ks[d * 64 + tx * 4];
            float qa[4] = {q4.x, q4.y, q4.z, q4.w};
            float ka[4] = {k4.x, k4.y, k4.z, k4.w};
            #pragma unroll
            for (int i = 0; i < 4; i++)
                #pragma unroll
                for (int j = 0; j < 4; j++) s[i][j] = fmaf(qa[i], ka[j], s[i][j]);
        }

        // online softmax update
        #pragma unroll
        for (int i = 0; i < 4; i++) {
            float rmax = fmaxf(fmaxf(s[i][0], s[i][1]), fmaxf(s[i][2], s[i][3]));
            #pragma unroll
            for (int m = 1; m < 16; m <<= 1)
                rmax = fmaxf(rmax, __shfl_xor_sync(0xffffffffu, rmax, m));
            float mnew = fmaxf(mrow[i], rmax);
            float alpha = exp2f(mrow[i] - mnew);
            mrow[i] = mnew;
            float rs = 0.0f;
            #pragma unroll
            for (int j = 0; j < 4; j++) {
                s[i][j] = exp2f(s[i][j] - mnew);
                rs += s[i][j];
            }
            #pragma unroll
            for (int m = 1; m < 16; m <<= 1)
                rs += __shfl_xor_sync(0xffffffffu, rs, m);
            lrow[i] = lrow[i] * alpha + rs;
            #pragma unroll
            for (int j = 0; j < 4; j++) o[i][j] *= alpha;
        }

        // O += P V : shfl-broadcast p fragments (source lane owns key kk)
        for (int kk4 = 0; kk4 < 16; kk4++) {
            int src = (lane & 16) | kk4;
            #pragma unroll
            for (int u = 0; u < 4; u++) {
                float4 v4 = *(const float4*)&Vs[(kk4 * 4 + u) * 64 + tx * 4];
                float pb0 = __shfl_sync(0xffffffffu, s[0][u], src);
                float pb1 = __shfl_sync(0xffffffffu, s[1][u], src);
                float pb2 = __shfl_sync(0xffffffffu, s[2][u], src);
                float pb3 = __shfl_sync(0xffffffffu, s[3][u], src);
                o[0][0] = fmaf(pb0, v4.x, o[0][0]); o[0][1] = fmaf(pb0, v4.y, o[0][1]);
                o[0][2] = fmaf(pb0, v4.z, o[0][2]); o[0][3] = fmaf(pb0, v4.w, o[0][3]);
                o[1][0] = fmaf(pb1, v4.x, o[1][0]); o[1][1] = fmaf(pb1, v4.y, o[1][1]);
                o[1][2] = fmaf(pb1, v4.z, o[1][2]); o[1][3] = fmaf(pb1, v4.w, o[1][3]);
                o[2][0] = fmaf(pb2, v4.x, o[2][0]); o[2][1] = fmaf(pb2, v4.y, o[2][1]);
                o[2][2] = fmaf(pb2, v4.z, o[2][2]); o[2][3] = fmaf(pb2, v4.w, o[2][3]);
                o[3][0] = fmaf(pb3, v4.x, o[3][0]); o[3][1] = fmaf(pb3, v4.y, o[3][1]);
                o[3][2] = fmaf(pb3, v4.z, o[3][2]); o[3][3] = fmaf(pb3, v4.w, o[3][3]);
            }
        }
    }

    // epilogue: normalize and write transposed [i][n] via smem staging
    #pragma unroll
    for (int i = 0; i < 4; i++) {
        float invl = 1.0f / lrow[i];
        #pragma unroll
        for (int j = 0; j < 4; j++) o[i][j] *= invl;
    }
    __syncthreads();
    #pragma unroll
    for (int i = 0; i < 4; i++)
        #pragma unroll
        for (int j = 0; j < 4; j++)
            Qs[(tx * 4 + j) * 64 + ty * 4 + i] = o[i][j];
    __syncthreads();
    #pragma unroll
    for (int it = 0; it < 16; it++) {
        int idx = tid + it * 256;
        int d = idx >> 6, ml = idx & 63;
        g_attnT[(h * DIM_HEAD + d) * N_SEQ + m0 + ml] = Qs[idx];
    }
}

// ---------------------------------------------------------------------------
// Kernel 3: transpose w_out [j][i] -> g_wT [i][j]
// ---------------------------------------------------------------------------
__global__ __launch_bounds__(256) void transpose_w_kernel(const float* __restrict__ w)
{
    __shared__ float t[64 * 65];
    int j0 = blockIdx.x * 64, i0 = blockIdx.y * 64;
    #pragma unroll
    for (int it = 0; it < 16; it++) {
        int idx = threadIdx.x + it * 256;
        int jl = idx >> 6, il = idx & 63;
        t[jl * 65 + il] = w[(j0 + jl) * DIM + i0 + il];
    }
    __syncthreads();
    #pragma unroll
    for (int it = 0; it < 16; it++) {
        int idx = threadIdx.x + it * 256;
        int il = idx >> 6, jl = idx & 63;
        g_wT[(i0 + il) * DIM + j0 + jl] = t[jl * 65 + il];
    }
}

// ---------------------------------------------------------------------------
// Kernel 4: projection GEMM: out[n][j] = sum_i attn[n][i] * w[j][i] + b[j]
// Both operands K-outer in smem, 64x64 tiles, 4x4 fragments, float4 loads.
// ---------------------------------------------------------------------------
__global__ __launch_bounds__(256) void proj_kernel(
    const float* __restrict__ b_out, float* __restrict__ out)
{
    __shared__ float As[64 * 64];  // [kk][m]
    __shared__ float Ws[64 * 64];  // [kk][j]
    int m0 = blockIdx.x * 64, j0 = blockIdx.y * 64;
    int tid = threadIdx.x;
    int tx = tid & 15, ty = tid >> 4;

    float acc[4][4];
    #pragma unroll
    for (int i = 0; i < 4; i++)
        #pragma unroll
        for (int j = 0; j < 4; j++) acc[i][j] = 0.0f;

    for (int k0 = 0; k0 < DIM; k0 += 64) {
        __syncthreads();
        #pragma unroll
        for (int it = 0; it < 16; it++) {
            int idx = tid + it * 256;
            int kk = idx >> 6, ml = idx & 63;
            As[idx] = g_attnT[(k0 + kk) * N_SEQ + m0 + ml];
            Ws[idx] = g_wT[(k0 + kk) * DIM + j0 + ml];
        }
        __syncthreads();
        #pragma unroll 8
        for (int kk = 0; kk < 64; kk++) {
            float4 a4 = *(const float4*)&As[kk * 64 + ty * 4];
            float4 w4 = *(const float4*)&Ws[kk * 64 + tx * 4];
            float aa[4] = {a4.x, a4.y, a4.z, a4.w};
            float ww[4] = {w4.x, w4.y, w4.z, w4.w};
            #pragma unroll
            for (int i = 0; i < 4; i++)
                #pragma unroll
                for (int j = 0; j < 4; j++) acc[i][j] = fmaf(aa[i], ww[j], acc[i][j]);
        }
    }

    float4 bb = *(const float4*)&b_out[j0 + tx * 4];
    #pragma unroll
    for (int i = 0; i < 4; i++) {
        float4 r;
        r.x = acc[i][0] + bb.x;
        r.y = acc[i][1] + bb.y;
        r.z = acc[i][2] + bb.z;
        r.w = acc[i][3] + bb.w;
        *(float4*)&out[(size_t)(m0 + ty * 4 + i) * DIM + j0 + tx * 4] = r;
    }
}

// ---------------------------------------------------------------------------
extern "C" void kernel_launch(void* const* d_in, const int* in_sizes, int n_in,
                              void* d_out, int out_size)
{
    const float* q        = (const float*)d_in[0];
    const float* k        = (const float*)d_in[1];
    const float* v        = (const float*)d_in[2];
    const float* qk_scale = (const float*)d_in[3];
    const float* w_out    = (const float*)d_in[4];
    const float* b_out    = (const float*)d_in[5];
    float* out = (float*)d_out;

    rope_table_kernel<<<(N_SEQ * 32 + 255) / 256, 256>>>();
    prep_kernel<<<dim3(N_SEQ / 64, N_HEADS, 2), 256>>>(q, k, qk_scale);
    transpose_w_kernel<<<dim3(DIM / 64, DIM / 64), 256>>>(w_out);
    attn_kernel<<<dim3(N_SEQ / 64, N_HEADS), 256>>>(v);
    proj_kernel<<<dim3(N_SEQ / 64, DIM / 64), 256>>>(b_out, out);
}

// round 6
// speedup vs baseline: 1.9497x; 1.8479x over previous
#include <cuda_runtime.h>
#include <math.h>
#include <stdint.h>

#define N_SEQ 4096
#define N_HEADS 16
#define DIM_HEAD 64
#define DIM 1024
#define CMAX 18.5f

// ---------------- scratch (device globals; no allocation allowed) ----------
__device__ float g_qhi[N_HEADS * N_SEQ * DIM_HEAD];  // [h][n][d] rope+norm+scale(+0.125*log2e), tf32-rna hi
__device__ float g_qlo[N_HEADS * N_SEQ * DIM_HEAD];  // fp32 residual
__device__ float g_khi[N_HEADS * N_SEQ * DIM_HEAD];
__device__ float g_klo[N_HEADS * N_SEQ * DIM_HEAD];
__device__ float g_vr [N_SEQ * DIM];                 // v, tf32-rna, natural [n][dim]
__device__ float g_wr [DIM * DIM];                   // w_out, tf32-rna, natural [j][i]
__device__ float g_attn[N_SEQ * DIM];                // attention out, tf32-rna, [n][dim]
__device__ float g_cos[N_SEQ * 32];
__device__ float g_sin[N_SEQ * 32];

// ---------------- helpers ---------------------------------------------------
__device__ __forceinline__ uint32_t smem_u32(const void* p) {
    uint32_t a;
    asm("{ .reg .u64 t; cvta.to.shared.u64 t, %1; cvt.u32.u64 %0, t; }" : "=r"(a) : "l"(p));
    return a;
}
__device__ __forceinline__ float tf32_rna(float x) {
    uint32_t r;
    asm("cvt.rna.tf32.f32 %0, %1;" : "=r"(r) : "f"(x));
    return __uint_as_float(r);
}
// m16n8k8 tf32 warp MMA (baseline PTX, sm_80+; target-safe on sm_103)
__device__ __forceinline__ void mma8(float* c,
    uint32_t a0, uint32_t a1, uint32_t a2, uint32_t a3,
    uint32_t b0, uint32_t b1)
{
    asm volatile(
        "mma.sync.aligned.m16n8k8.row.col.f32.tf32.tf32.f32 "
        "{%0,%1,%2,%3}, {%4,%5,%6,%7}, {%8,%9}, {%0,%1,%2,%3};"
        : "+f"(c[0]), "+f"(c[1]), "+f"(c[2]), "+f"(c[3])
        : "r"(a0), "r"(a1), "r"(a2), "r"(a3), "r"(b0), "r"(b1));
}
__device__ __forceinline__ void cp16(uint32_t dst, const void* src) {
    asm volatile("cp.async.cg.shared.global [%0], [%1], 16;" :: "r"(dst), "l"(src));
}
#define CP_COMMIT() asm volatile("cp.async.commit_group;" ::: "memory")
#define CP_WAIT1()  asm volatile("cp.async.wait_group 1;" ::: "memory")
#define CP_WAIT0()  asm volatile("cp.async.wait_group 0;" ::: "memory")

// ---------------------------------------------------------------------------
// Kernel 0: RoPE tables (double sincos of the fp32-rounded angle)
// ---------------------------------------------------------------------------
__global__ void rope_table_kernel() {
    int idx = blockIdx.x * blockDim.x + threadIdx.x;
    if (idx >= N_SEQ * 32) return;
    int n = idx >> 5, l = idx & 31;
    float invf = (float)exp(-((double)l / 32.0) * log(10000.0));
    float ang = (float)n * invf;
    double s, c;
    sincos((double)ang, &s, &c);
    g_cos[idx] = (float)c;
    g_sin[idx] = (float)s;
}

// ---------------------------------------------------------------------------
// Kernel 1: prep q/k: RoPE + l2norm + qk_scale (+0.125*log2e into q),
// tf32 hi/lo split, layout [h][n][d]. One warp per (token, head).
// ---------------------------------------------------------------------------
__global__ __launch_bounds__(256) void prep_qk_kernel(
    const float* __restrict__ q, const float* __restrict__ k,
    const float* __restrict__ qk_scale)
{
    int wi = blockIdx.x * 8 + (threadIdx.x >> 5);   // 0..65535
    int l = threadIdx.x & 31;
    int h = wi & 15;
    int n = wi >> 4;
    const float* src = (blockIdx.y == 0) ? q : k;
    float* dhi = (blockIdx.y == 0) ? g_qhi : g_khi;
    float* dlo = (blockIdx.y == 0) ? g_qlo : g_klo;
    float fold = (blockIdx.y == 0) ? (0.125f * 1.4426950408889634f) : 1.0f;

    float2 x = ((const float2*)(src + (size_t)n * DIM + h * DIM_HEAD))[l];
    float2 sc = ((const float2*)qk_scale)[l];
    float c = g_cos[n * 32 + l], s = g_sin[n * 32 + l];
    float orr = x.x * c - x.y * s;
    float oii = x.x * s + x.y * c;
    float sq = orr * orr + oii * oii;
    #pragma unroll
    for (int m = 16; m; m >>= 1) sq += __shfl_xor_sync(0xffffffffu, sq, m);
    float f = fold / fmaxf(sqrtf(sq), 1e-12f);
    float a = orr * f * sc.x;
    float b = oii * f * sc.y;
    float ah = tf32_rna(a), bh = tf32_rna(b);
    size_t o = ((size_t)h * N_SEQ + n) * DIM_HEAD + 2 * l;
    *(float2*)(dhi + o) = make_float2(ah, bh);
    *(float2*)(dlo + o) = make_float2(a - ah, b - bh);
}

// ---------------------------------------------------------------------------
// Kernel 2a/2b: elementwise rna rounding of v and w_out
// ---------------------------------------------------------------------------
__global__ __launch_bounds__(256) void vround_kernel(const float* __restrict__ v) {
    int i = blockIdx.x * 256 + threadIdx.x;
    float4 x = ((const float4*)v)[i];
    ((float4*)g_vr)[i] = make_float4(tf32_rna(x.x), tf32_rna(x.y), tf32_rna(x.z), tf32_rna(x.w));
}
__global__ __launch_bounds__(256) void wround_kernel(const float* __restrict__ w) {
    int i = blockIdx.x * 256 + threadIdx.x;
    float4 x = ((const float4*)w)[i];
    ((float4*)g_wr)[i] = make_float4(tf32_rna(x.x), tf32_rna(x.y), tf32_rna(x.z), tf32_rna(x.w));
}

// ---------------------------------------------------------------------------
// Kernel 3: flash attention on mma.sync tf32.
// CTA = 128 q-rows x 1 head; 8 warps x 16 rows; 64 KV tiles of 64 keys,
// double-buffered via cp.async. QK = 3xtf32, PV = tf32 (all operands rna'd).
// Fixed-max softmax (CMAX), O accumulated in C frags across tiles.
// smem strides: Q/K 68 (bank=4r+c), V 72 (bank=8c+g) -> conflict-free frags.
// SMEM floats: Qhi 0..8704, Qlo 8704..17408, KV buf b at 17408 + b*13312
//   (Khi +0 (64x68), Klo +4352, V +8704 (64x72)); total 44032 fl = 176128 B.
// ---------------------------------------------------------------------------
#define KV_OFF 17408
#define KV_STRF 13312
#define ATTN_SMEM_BYTES ((KV_OFF + 2 * KV_STRF) * 4)

__device__ __forceinline__ void issue_kv(uint32_t kv_u32, int h, int k0, int tid)
{
    #pragma unroll
    for (int j = 0; j < 4; j++) {
        int id = tid + j * 256;       // 0..1023
        int row = id >> 4;            // 0..63
        int c4 = (id & 15) * 4;       // 0,4,..,60
        const float* skh = g_khi + ((size_t)h * N_SEQ + k0 + row) * DIM_HEAD + c4;
        const float* skl = g_klo + ((size_t)h * N_SEQ + k0 + row) * DIM_HEAD + c4;
        const float* sv  = g_vr + (size_t)(k0 + row) * DIM + h * DIM_HEAD + c4;
        cp16(kv_u32 + (uint32_t)(row * 68 + c4) * 4u, skh);
        cp16(kv_u32 + (uint32_t)(4352 + row * 68 + c4) * 4u, skl);
        cp16(kv_u32 + (uint32_t)(8704 + row * 72 + c4) * 4u, sv);
    }
}

__global__ __launch_bounds__(256) void attn_kernel()
{
    extern __shared__ float sm[];
    float* Qhi = sm;
    float* Qlo = sm + 8704;
    uint32_t kvu0 = smem_u32(sm) + KV_OFF * 4u;

    int tid = threadIdx.x;
    int warp = tid >> 5, lane = tid & 31;
    int r = lane >> 2, c = lane & 3;
    int h = blockIdx.y, m0 = blockIdx.x * 128;

    // Q tiles into smem (stride 68)
    {
        int qr = tid >> 1;
        int c0 = (tid & 1) * 32;
        const float4* qh = (const float4*)(g_qhi + ((size_t)h * N_SEQ + m0 + qr) * DIM_HEAD + c0);
        const float4* ql = (const float4*)(g_qlo + ((size_t)h * N_SEQ + m0 + qr) * DIM_HEAD + c0);
        #pragma unroll
        for (int j = 0; j < 8; j++) {
            *(float4*)&Qhi[qr * 68 + c0 + j * 4] = qh[j];
            *(float4*)&Qlo[qr * 68 + c0 + j * 4] = ql[j];
        }
    }

    issue_kv(kvu0, h, 0, tid);                  CP_COMMIT();
    issue_kv(kvu0 + KV_STRF * 4u, h, 64, tid);  CP_COMMIT();

    float s[8][4], o[8][4];
    float lsum0 = 0.0f, lsum1 = 0.0f;
    #pragma unroll
    for (int nf = 0; nf < 8; nf++)
        #pragma unroll
        for (int e = 0; e < 4; e++) o[nf][e] = 0.0f;

    const float* qhB = &Qhi[(warp * 16 + r) * 68 + c];
    const float* qlB = &Qlo[(warp * 16 + r) * 68 + c];
    int src0 = (lane & ~3) | (c >> 1);
    int src1 = src0 + 2;
    bool odd = (c & 1) != 0;

    for (int t = 0; t < 64; t++) {
        if (t == 63) { CP_WAIT0(); } else { CP_WAIT1(); }
        __syncthreads();
        float* kv  = sm + KV_OFF + (t & 1) * KV_STRF;
        float* Khi = kv;
        float* Klo = kv + 4352;
        float* Vb  = kv + 8704;

        #pragma unroll
        for (int nf = 0; nf < 8; nf++)
            #pragma unroll
            for (int e = 0; e < 4; e++) s[nf][e] = 0.0f;

        // ---- S = Q K^T, 3xtf32 ----
        #pragma unroll
        for (int ks = 0; ks < 8; ks++) {
            int k0 = ks * 8;
            uint32_t ah0 = __float_as_uint(qhB[k0]);
            uint32_t ah1 = __float_as_uint(qhB[k0 + 8 * 68]);
            uint32_t ah2 = __float_as_uint(qhB[k0 + 4]);
            uint32_t ah3 = __float_as_uint(qhB[k0 + 8 * 68 + 4]);
            uint32_t al0 = __float_as_uint(qlB[k0]);
            uint32_t al1 = __float_as_uint(qlB[k0 + 8 * 68]);
            uint32_t al2 = __float_as_uint(qlB[k0 + 4]);
            uint32_t al3 = __float_as_uint(qlB[k0 + 8 * 68 + 4]);
            #pragma unroll
            for (int nf = 0; nf < 8; nf++) {
                const float* kb = &Khi[(nf * 8 + r) * 68 + k0 + c];
                const float* lb = &Klo[(nf * 8 + r) * 68 + k0 + c];
                uint32_t bh0 = __float_as_uint(kb[0]);
                uint32_t bh1 = __float_as_uint(kb[4]);
                uint32_t bl0 = __float_as_uint(lb[0]);
                uint32_t bl1 = __float_as_uint(lb[4]);
                mma8(s[nf], ah0, ah1, ah2, ah3, bh0, bh1);
                mma8(s[nf], ah0, ah1, ah2, ah3, bl0, bl1);
                mma8(s[nf], al0, al1, al2, al3, bh0, bh1);
            }
        }

        // ---- softmax numerators (log2 units, fixed shift); rna BEFORE sum
        //      so PV numerator and denominator share the same rounding ----
        #pragma unroll
        for (int nf = 0; nf < 8; nf++) {
            s[nf][0] = tf32_rna(exp2f(s[nf][0] - CMAX));
            s[nf][1] = tf32_rna(exp2f(s[nf][1] - CMAX));
            s[nf][2] = tf32_rna(exp2f(s[nf][2] - CMAX));
            s[nf][3] = tf32_rna(exp2f(s[nf][3] - CMAX));
            lsum0 += s[nf][0] + s[nf][1];
            lsum1 += s[nf][2] + s[nf][3];
        }

        // ---- O += P V : shfl-relayout C-frags -> A-frags, tf32 PV ----
        #pragma unroll
        for (int ks = 0; ks < 8; ks++) {
            float v00 = __shfl_sync(0xffffffffu, s[ks][0], src0);
            float v01 = __shfl_sync(0xffffffffu, s[ks][1], src0);
            float v10 = __shfl_sync(0xffffffffu, s[ks][2], src0);
            float v11 = __shfl_sync(0xffffffffu, s[ks][3], src0);
            float w00 = __shfl_sync(0xffffffffu, s[ks][0], src1);
            float w01 = __shfl_sync(0xffffffffu, s[ks][1], src1);
            float w10 = __shfl_sync(0xffffffffu, s[ks][2], src1);
            float w11 = __shfl_sync(0xffffffffu, s[ks][3], src1);
            uint32_t a0 = __float_as_uint(odd ? v01 : v00);   // P[r][8ks+c]
            uint32_t a1 = __float_as_uint(odd ? v11 : v10);   // P[r+8][8ks+c]
            uint32_t a2 = __float_as_uint(odd ? w01 : w00);   // P[r][8ks+c+4]
            uint32_t a3 = __float_as_uint(odd ? w11 : w10);   // P[r+8][8ks+c+4]
            const float* vb = &Vb[(ks * 8 + c) * 72 + r];
            #pragma unroll
            for (int nf = 0; nf < 8; nf++) {
                uint32_t b0 = __float_as_uint(vb[nf * 8]);
                uint32_t b1 = __float_as_uint(vb[4 * 72 + nf * 8]);
                mma8(o[nf], a0, a1, a2, a3, b0, b1);
            }
        }

        __syncthreads();
        if (t + 2 < 64) {
            issue_kv(kvu0 + (uint32_t)(t & 1) * KV_STRF * 4u, h, (t + 2) * 64, tid);
            CP_COMMIT();
        }
    }

    // ---- epilogue: row sums across the quad, normalize, rna, store ----
    lsum0 += __shfl_xor_sync(0xffffffffu, lsum0, 1);
    lsum0 += __shfl_xor_sync(0xffffffffu, lsum0, 2);
    lsum1 += __shfl_xor_sync(0xffffffffu, lsum1, 1);
    lsum1 += __shfl_xor_sync(0xffffffffu, lsum1, 2);
    float inv0 = 1.0f / lsum0, inv1 = 1.0f / lsum1;
    int row0 = m0 + warp * 16 + r;
    #pragma unroll
    for (int nf = 0; nf < 8; nf++) {
        int col = h * DIM_HEAD + nf * 8 + 2 * c;
        float2 x0 = make_float2(tf32_rna(o[nf][0] * inv0), tf32_rna(o[nf][1] * inv0));
        float2 x1 = make_float2(tf32_rna(o[nf][2] * inv1), tf32_rna(o[nf][3] * inv1));
        *(float2*)&g_attn[(size_t)row0 * DIM + col] = x0;
        *(float2*)&g_attn[(size_t)(row0 + 8) * DIM + col] = x1;
    }
}

// ---------------------------------------------------------------------------
// Kernel 4: projection GEMM on mma.sync tf32.
// out[n][j] = sum_i attn[n][i] * w[j][i] + b[j].
// CTA tile 128x128, 8 warps as 4(m) x 2(n): warp tile 32x64.
// k-chunks of 64, cp.async double-buffered. w used in NATIVE [j][i] layout
// as the col-major B operand (no transpose kernel).
// smem: buf b at b*17408: As 128x68 (+0), Ws 128x68 (+8704). 139264 B.
// ---------------------------------------------------------------------------
#define PROJ_STRF 17408
#define PROJ_SMEM_BYTES (2 * PROJ_STRF * 4)

__device__ __forceinline__ void issue_proj(uint32_t base, int m0, int j0, int k0, int tid)
{
    #pragma unroll
    for (int j = 0; j < 8; j++) {
        int id = tid + j * 256;       // 0..2047
        int row = id >> 4;            // 0..127
        int c4 = (id & 15) * 4;
        cp16(base + (uint32_t)(row * 68 + c4) * 4u,
             g_attn + (size_t)(m0 + row) * DIM + k0 + c4);
        cp16(base + (uint32_t)(8704 + row * 68 + c4) * 4u,
             g_wr + (size_t)(j0 + row) * DIM + k0 + c4);
    }
}

__global__ __launch_bounds__(256) void proj_kernel(
    const float* __restrict__ b_out, float* __restrict__ out)
{
    extern __shared__ float sm[];
    uint32_t smu = smem_u32(sm);
    int tid = threadIdx.x;
    int warp = tid >> 5, lane = tid & 31;
    int r = lane >> 2, c = lane & 3;
    int mw = warp >> 1, nw = warp & 1;
    int m0 = blockIdx.x * 128, j0 = blockIdx.y * 128;

    float acc[2][8][4];
    #pragma unroll
    for (int mf = 0; mf < 2; mf++)
        #pragma unroll
        for (int nf = 0; nf < 8; nf++)
            #pragma unroll
            for (int e = 0; e < 4; e++) acc[mf][nf][e] = 0.0f;

    issue_proj(smu, m0, j0, 0, tid);                    CP_COMMIT();
    issue_proj(smu + PROJ_STRF * 4u, m0, j0, 64, tid);  CP_COMMIT();

    for (int ch = 0; ch < 16; ch++) {
        if (ch == 15) { CP_WAIT0(); } else { CP_WAIT1(); }
        __syncthreads();
        float* As = sm + (ch & 1) * PROJ_STRF;
        float* Ws = As + 8704;

        #pragma unroll
        for (int ks = 0; ks < 8; ks++) {
            int k0 = ks * 8;
            uint32_t a[2][4];
            #pragma unroll
            for (int mf = 0; mf < 2; mf++) {
                const float* ab = &As[(mw * 32 + mf * 16 + r) * 68 + k0 + c];
                a[mf][0] = __float_as_uint(ab[0]);
                a[mf][1] = __float_as_uint(ab[8 * 68]);
                a[mf][2] = __float_as_uint(ab[4]);
                a[mf][3] = __float_as_uint(ab[8 * 68 + 4]);
            }
            #pragma unroll
            for (int nf = 0; nf < 8; nf++) {
                const float* wb = &Ws[(nw * 64 + nf * 8 + r) * 68 + k0 + c];
                uint32_t b0 = __float_as_uint(wb[0]);
                uint32_t b1 = __float_as_uint(wb[4]);
                mma8(acc[0][nf], a[0][0], a[0][1], a[0][2], a[0][3], b0, b1);
                mma8(acc[1][nf], a[1][0], a[1][1], a[1][2], a[1][3], b0, b1);
            }
        }

        __syncthreads();
        if (ch + 2 < 16) {
            issue_proj(smu + (uint32_t)(ch & 1) * PROJ_STRF * 4u, m0, j0, (ch + 2) * 64, tid);
            CP_COMMIT();
        }
    }

    #pragma unroll
    for (int mf = 0; mf < 2; mf++) {
        int row = m0 + mw * 32 + mf * 16 + r;
        #pragma unroll
        for (int nf = 0; nf < 8; nf++) {
            int col = j0 + nw * 64 + nf * 8 + 2 * c;
            float2 bb = *(const float2*)&b_out[col];
            *(float2*)&out[(size_t)row * DIM + col] =
                make_float2(acc[mf][nf][0] + bb.x, acc[mf][nf][1] + bb.y);
            *(float2*)&out[(size_t)(row + 8) * DIM + col] =
                make_float2(acc[mf][nf][2] + bb.x, acc[mf][nf][3] + bb.y);
        }
    }
}

// ---------------------------------------------------------------------------
extern "C" void kernel_launch(void* const* d_in, const int* in_sizes, int n_in,
                              void* d_out, int out_size)
{
    const float* q        = (const float*)d_in[0];
    const float* k        = (const float*)d_in[1];
    const float* v        = (const float*)d_in[2];
    const float* qk_scale = (const float*)d_in[3];
    const float* w_out    = (const float*)d_in[4];
    const float* b_out    = (const float*)d_in[5];
    float* out = (float*)d_out;

    cudaFuncSetAttribute(attn_kernel,
                         cudaFuncAttributeMaxDynamicSharedMemorySize, ATTN_SMEM_BYTES);
    cudaFuncSetAttribute(proj_kernel,
                         cudaFuncAttributeMaxDynamicSharedMemorySize, PROJ_SMEM_BYTES);

    rope_table_kernel<<<(N_SEQ * 32 + 255) / 256, 256>>>();
    prep_qk_kernel<<<dim3(8192, 2), 256>>>(q, k, qk_scale);
    vround_kernel<<<(N_SEQ * DIM / 4) / 256, 256>>>(v);
    wround_kernel<<<(DIM * DIM / 4) / 256, 256>>>(w_out);
    attn_kernel<<<dim3(N_SEQ / 128, N_HEADS), 256, ATTN_SMEM_BYTES>>>();
    proj_kernel<<<dim3(N_SEQ / 128, DIM / 128), 256, PROJ_SMEM_BYTES>>>(b_out, out);
}

// round 8
// speedup vs baseline: 3.2834x; 1.6841x over previous
#include <cuda_runtime.h>
#include <cuda_bf16.h>
#include <math.h>
#include <stdint.h>

#define N_SEQ 4096
#define N_HEADS 16
#define DIM_HEAD 64
#define DIM 1024
#define CMAX 18.5f

// ---------------- scratch (device globals; no allocation allowed) ----------
// q/k after rope+l2norm+qk_scale (+0.125*log2e folded into q), stored as
// packed bf16 pairs: hi = bf16(x), lo = bf16(x - hi). Word w holds dims
// (2w, 2w+1) of a 64-dim head row. Layout [h][n][32 words].
__device__ uint32_t g_qhib[N_HEADS * N_SEQ * 32];
__device__ uint32_t g_qlob[N_HEADS * N_SEQ * 32];
__device__ uint32_t g_khib[N_HEADS * N_SEQ * 32];
__device__ uint32_t g_klob[N_HEADS * N_SEQ * 32];
__device__ float g_vr [N_SEQ * DIM];                 // v, tf32-rna, natural [n][dim]
__device__ float g_wr [DIM * DIM];                   // w_out, tf32-rna, natural [j][i]
__device__ float g_attn[N_SEQ * DIM];                // attention out, tf32-rna, [n][dim]
__device__ float g_cos[N_SEQ * 32];
__device__ float g_sin[N_SEQ * 32];

// ---------------- helpers ---------------------------------------------------
__device__ __forceinline__ uint32_t smem_u32(const void* p) {
    uint32_t a;
    asm("{ .reg .u64 t; cvta.to.shared.u64 t, %1; cvt.u32.u64 %0, t; }" : "=r"(a) : "l"(p));
    return a;
}
__device__ __forceinline__ float tf32_rna(float x) {
    uint32_t r;
    asm("cvt.rna.tf32.f32 %0, %1;" : "=r"(r) : "f"(x));
    return __uint_as_float(r);
}
__device__ __forceinline__ uint32_t packbf(float a, float b) {
    __nv_bfloat162 t = __floats2bfloat162_rn(a, b);   // a -> low half (dim 2l)
    return *(uint32_t*)&t;
}
// tf32 m16n8k8 (PV + projection)
__device__ __forceinline__ void mma8(float* c,
    uint32_t a0, uint32_t a1, uint32_t a2, uint32_t a3,
    uint32_t b0, uint32_t b1)
{
    asm volatile(
        "mma.sync.aligned.m16n8k8.row.col.f32.tf32.tf32.f32 "
        "{%0,%1,%2,%3}, {%4,%5,%6,%7}, {%8,%9}, {%0,%1,%2,%3};"
        : "+f"(c[0]), "+f"(c[1]), "+f"(c[2]), "+f"(c[3])
        : "r"(a0), "r"(a1), "r"(a2), "r"(a3), "r"(b0), "r"(b1));
}
// bf16 m16n8k16 (QK hi/lo passes)
__device__ __forceinline__ void mma16(float* c, const uint32_t* a,
                                      uint32_t b0, uint32_t b1)
{
    asm volatile(
        "mma.sync.aligned.m16n8k16.row.col.f32.bf16.bf16.f32 "
        "{%0,%1,%2,%3}, {%4,%5,%6,%7}, {%8,%9}, {%0,%1,%2,%3};"
        : "+f"(c[0]), "+f"(c[1]), "+f"(c[2]), "+f"(c[3])
        : "r"(a[0]), "r"(a[1]), "r"(a[2]), "r"(a[3]), "r"(b0), "r"(b1));
}
__device__ __forceinline__ void cp16(uint32_t dst, const void* src) {
    asm volatile("cp.async.cg.shared.global [%0], [%1], 16;" :: "r"(dst), "l"(src));
}
#define CP_COMMIT() asm volatile("cp.async.commit_group;" ::: "memory")
#define CP_WAIT1()  asm volatile("cp.async.wait_group 1;" ::: "memory")
#define CP_WAIT0()  asm volatile("cp.async.wait_group 0;" ::: "memory")

// ---------------------------------------------------------------------------
// Kernel 0: RoPE tables (double sincos of the fp32-rounded angle)
// ---------------------------------------------------------------------------
__global__ void rope_table_kernel() {
    int idx = blockIdx.x * blockDim.x + threadIdx.x;
    if (idx >= N_SEQ * 32) return;
    int n = idx >> 5, l = idx & 31;
    float invf = (float)exp(-((double)l / 32.0) * log(10000.0));
    float ang = (float)n * invf;
    double s, c;
    sincos((double)ang, &s, &c);
    g_cos[idx] = (float)c;
    g_sin[idx] = (float)s;
}

// ---------------------------------------------------------------------------
// Kernel 1: prep q/k: RoPE + l2norm + qk_scale (+0.125*log2e into q),
// bf16 hi/lo split, packed-pair layout [h][n][32w]. One warp per (token, head).
// ---------------------------------------------------------------------------
__global__ __launch_bounds__(256) void prep_qk_kernel(
    const float* __restrict__ q, const float* __restrict__ k,
    const float* __restrict__ qk_scale)
{
    int wi = blockIdx.x * 8 + (threadIdx.x >> 5);   // 0..65535
    int l = threadIdx.x & 31;
    int h = wi & 15;
    int n = wi >> 4;
    const float* src = (blockIdx.y == 0) ? q : k;
    uint32_t* dhi = (blockIdx.y == 0) ? g_qhib : g_khib;
    uint32_t* dlo = (blockIdx.y == 0) ? g_qlob : g_klob;
    float fold = (blockIdx.y == 0) ? (0.125f * 1.4426950408889634f) : 1.0f;

    float2 x = ((const float2*)(src + (size_t)n * DIM + h * DIM_HEAD))[l];
    float2 sc = ((const float2*)qk_scale)[l];
    float c = g_cos[n * 32 + l], s = g_sin[n * 32 + l];
    float orr = x.x * c - x.y * s;
    float oii = x.x * s + x.y * c;
    float sq = orr * orr + oii * oii;
    #pragma unroll
    for (int m = 16; m; m >>= 1) sq += __shfl_xor_sync(0xffffffffu, sq, m);
    float f = fold / fmaxf(sqrtf(sq), 1e-12f);
    float a = orr * f * sc.x;
    float b = oii * f * sc.y;
    float ah = __bfloat162float(__float2bfloat16(a));
    float bh = __bfloat162float(__float2bfloat16(b));
    size_t o = ((size_t)h * N_SEQ + n) * 32 + l;
    dhi[o] = packbf(a, b);            // rn re-round == (ah, bh)
    dlo[o] = packbf(a - ah, b - bh);
}

// ---------------------------------------------------------------------------
// Kernel 2a/2b: elementwise rna rounding of v and w_out (tf32 operands)
// ---------------------------------------------------------------------------
__global__ __launch_bounds__(256) void vround_kernel(const float* __restrict__ v) {
    int i = blockIdx.x * 256 + threadIdx.x;
    float4 x = ((const float4*)v)[i];
    ((float4*)g_vr)[i] = make_float4(tf32_rna(x.x), tf32_rna(x.y), tf32_rna(x.z), tf32_rna(x.w));
}
__global__ __launch_bounds__(256) void wround_kernel(const float* __restrict__ w) {
    int i = blockIdx.x * 256 + threadIdx.x;
    float4 x = ((const float4*)w)[i];
    ((float4*)g_wr)[i] = make_float4(tf32_rna(x.x), tf32_rna(x.y), tf32_rna(x.z), tf32_rna(x.w));
}

// ---------------------------------------------------------------------------
// Kernel 3: flash attention. CTA = 128 q-rows x 1 head; 8 warps x 16 rows;
// 64 KV tiles of 64 keys, double-buffered via cp.async.
// S = 2xbf16 (hi*hi + hi*lo + lo*hi) on m16n8k16; PV = tf32 m16n8k8.
// Q A-fragments preloaded to registers (tile-invariant). Fixed-max softmax.
// SMEM per buffer: Khi 64x36w (+0, 9216B), Klo (+9216), V 64x72f (+18432,
// 18432B) => 36864B/buf, 73728B total.
// B-fragment word addressing for k16 step ks: word = ks*8 + c (and +4) —
// 16 dims = 8 packed words per step.
// ---------------------------------------------------------------------------
#define KV_STR_B 36864
#define ATTN_SMEM_BYTES (2 * KV_STR_B)

__device__ __forceinline__ void issue_kv(uint32_t base, int h, int k0, int tid)
{
    #pragma unroll
    for (int j = 0; j < 2; j++) {
        int id = tid + j * 256;       // 0..511
        int row = id >> 3;            // 0..63
        int ch = id & 7;              // 16B chunk
        const uint32_t* skh = g_khib + ((size_t)h * N_SEQ + k0 + row) * 32 + ch * 4;
        const uint32_t* skl = g_klob + ((size_t)h * N_SEQ + k0 + row) * 32 + ch * 4;
        cp16(base + (uint32_t)(row * 144 + ch * 16), skh);
        cp16(base + (uint32_t)(9216 + row * 144 + ch * 16), skl);
    }
    #pragma unroll
    for (int j = 0; j < 4; j++) {
        int id = tid + j * 256;       // 0..1023
        int row = id >> 4;
        int c4 = (id & 15) * 4;
        cp16(base + (uint32_t)(18432 + row * 288 + c4 * 4),
             g_vr + (size_t)(k0 + row) * DIM + h * DIM_HEAD + c4);
    }
}

__global__ __launch_bounds__(256) void attn_kernel()
{
    extern __shared__ char smb[];
    uint32_t kvu0 = smem_u32(smb);

    int tid = threadIdx.x;
    int warp = tid >> 5, lane = tid & 31;
    int r = lane >> 2, c = lane & 3;
    int h = blockIdx.y, m0 = blockIdx.x * 128;

    issue_kv(kvu0, h, 0, tid);             CP_COMMIT();
    issue_kv(kvu0 + KV_STR_B, h, 64, tid); CP_COMMIT();

    // Q fragments (hi/lo), tile-invariant: 4 k16-steps x 4 regs each
    uint32_t qhf[4][4], qlf[4][4];
    {
        const uint32_t* qh = g_qhib + ((size_t)h * N_SEQ + m0 + warp * 16 + r) * 32;
        const uint32_t* ql = g_qlob + ((size_t)h * N_SEQ + m0 + warp * 16 + r) * 32;
        #pragma unroll
        for (int ks = 0; ks < 4; ks++) {
            qhf[ks][0] = qh[ks * 8 + c];
            qhf[ks][1] = qh[256 + ks * 8 + c];
            qhf[ks][2] = qh[ks * 8 + c + 4];
            qhf[ks][3] = qh[256 + ks * 8 + c + 4];
            qlf[ks][0] = ql[ks * 8 + c];
            qlf[ks][1] = ql[256 + ks * 8 + c];
            qlf[ks][2] = ql[ks * 8 + c + 4];
            qlf[ks][3] = ql[256 + ks * 8 + c + 4];
        }
    }

    float s[8][4], o[8][4];
    float lsum0 = 0.0f, lsum1 = 0.0f;
    #pragma unroll
    for (int nf = 0; nf < 8; nf++)
        #pragma unroll
        for (int e = 0; e < 4; e++) o[nf][e] = 0.0f;

    int src0 = (lane & ~3) | (c >> 1);
    int src1 = src0 + 2;
    bool odd = (c & 1) != 0;

    for (int t = 0; t < 64; t++) {
        if (t == 63) { CP_WAIT0(); } else { CP_WAIT1(); }
        __syncthreads();
        char* buf = smb + (t & 1) * KV_STR_B;
        const uint32_t* KhiW = (const uint32_t*)buf;
        const uint32_t* KloW = KhiW + 2304;
        const float* Vb = (const float*)(buf + 18432);

        #pragma unroll
        for (int nf = 0; nf < 8; nf++)
            #pragma unroll
            for (int e = 0; e < 4; e++) s[nf][e] = 0.0f;

        // ---- S = Q K^T, 2xbf16 (3 passes, k16) ----
        #pragma unroll
        for (int ks = 0; ks < 4; ks++) {
            #pragma unroll
            for (int nf = 0; nf < 8; nf++) {
                const uint32_t* kb = KhiW + (nf * 8 + r) * 36 + ks * 8 + c;
                const uint32_t* lb = KloW + (nf * 8 + r) * 36 + ks * 8 + c;
                uint32_t bh0 = kb[0], bh1 = kb[4];
                uint32_t bl0 = lb[0], bl1 = lb[4];
                mma16(s[nf], qhf[ks], bh0, bh1);
                mma16(s[nf], qhf[ks], bl0, bl1);
                mma16(s[nf], qlf[ks], bh0, bh1);
            }
        }

        // ---- softmax numerators (log2 units, fixed shift); rna BEFORE sum
        //      so PV numerator and denominator share the same rounding ----
        #pragma unroll
        for (int nf = 0; nf < 8; nf++) {
            s[nf][0] = tf32_rna(exp2f(s[nf][0] - CMAX));
            s[nf][1] = tf32_rna(exp2f(s[nf][1] - CMAX));
            s[nf][2] = tf32_rna(exp2f(s[nf][2] - CMAX));
            s[nf][3] = tf32_rna(exp2f(s[nf][3] - CMAX));
            lsum0 += s[nf][0] + s[nf][1];
            lsum1 += s[nf][2] + s[nf][3];
        }

        // ---- O += P V : shfl-relayout C-frags -> A-frags, tf32 PV ----
        #pragma unroll
        for (int ks = 0; ks < 8; ks++) {
            float v00 = __shfl_sync(0xffffffffu, s[ks][0], src0);
            float v01 = __shfl_sync(0xffffffffu, s[ks][1], src0);
            float v10 = __shfl_sync(0xffffffffu, s[ks][2], src0);
            float v11 = __shfl_sync(0xffffffffu, s[ks][3], src0);
            float w00 = __shfl_sync(0xffffffffu, s[ks][0], src1);
            float w01 = __shfl_sync(0xffffffffu, s[ks][1], src1);
            float w10 = __shfl_sync(0xffffffffu, s[ks][2], src1);
            float w11 = __shfl_sync(0xffffffffu, s[ks][3], src1);
            uint32_t a0 = __float_as_uint(odd ? v01 : v00);
            uint32_t a1 = __float_as_uint(odd ? v11 : v10);
            uint32_t a2 = __float_as_uint(odd ? w01 : w00);
            uint32_t a3 = __float_as_uint(odd ? w11 : w10);
            const float* vb = &Vb[(ks * 8 + c) * 72 + r];
            #pragma unroll
            for (int nf = 0; nf < 8; nf++) {
                uint32_t b0 = __float_as_uint(vb[nf * 8]);
                uint32_t b1 = __float_as_uint(vb[4 * 72 + nf * 8]);
                mma8(o[nf], a0, a1, a2, a3, b0, b1);
            }
        }

        __syncthreads();
        if (t + 2 < 64) {
            issue_kv(kvu0 + (uint32_t)(t & 1) * KV_STR_B, h, (t + 2) * 64, tid);
            CP_COMMIT();
        }
    }

    // ---- epilogue: quad row sums, normalize, rna, store ----
    lsum0 += __shfl_xor_sync(0xffffffffu, lsum0, 1);
    lsum0 += __shfl_xor_sync(0xffffffffu, lsum0, 2);
    lsum1 += __shfl_xor_sync(0xffffffffu, lsum1, 1);
    lsum1 += __shfl_xor_sync(0xffffffffu, lsum1, 2);
    float inv0 = 1.0f / lsum0, inv1 = 1.0f / lsum1;
    int row0 = m0 + warp * 16 + r;
    #pragma unroll
    for (int nf = 0; nf < 8; nf++) {
        int col = h * DIM_HEAD + nf * 8 + 2 * c;
        float2 x0 = make_float2(tf32_rna(o[nf][0] * inv0), tf32_rna(o[nf][1] * inv0));
        float2 x1 = make_float2(tf32_rna(o[nf][2] * inv1), tf32_rna(o[nf][3] * inv1));
        *(float2*)&g_attn[(size_t)row0 * DIM + col] = x0;
        *(float2*)&g_attn[(size_t)(row0 + 8) * DIM + col] = x1;
    }
}

// ---------------------------------------------------------------------------
// Kernel 4: projection GEMM on mma.sync tf32 (unchanged, validated R5).
// out[n][j] = sum_i attn[n][i] * w[j][i] + b[j]. CTA 128x128, warps 4x2.
// ---------------------------------------------------------------------------
#define PROJ_STRF 17408
#define PROJ_SMEM_BYTES (2 * PROJ_STRF * 4)

__device__ __forceinline__ void issue_proj(uint32_t base, int m0, int j0, int k0, int tid)
{
    #pragma unroll
    for (int j = 0; j < 8; j++) {
        int id = tid + j * 256;
        int row = id >> 4;
        int c4 = (id & 15) * 4;
        cp16(base + (uint32_t)(row * 68 + c4) * 4u,
             g_attn + (size_t)(m0 + row) * DIM + k0 + c4);
        cp16(base + (uint32_t)(8704 + row * 68 + c4) * 4u,
             g_wr + (size_t)(j0 + row) * DIM + k0 + c4);
    }
}

__global__ __launch_bounds__(256) void proj_kernel(
    const float* __restrict__ b_out, float* __restrict__ out)
{
    extern __shared__ float sm[];
    uint32_t smu = smem_u32(sm);
    int tid = threadIdx.x;
    int warp = tid >> 5, lane = tid & 31;
    int r = lane >> 2, c = lane & 3;
    int mw = warp >> 1, nw = warp & 1;
    int m0 = blockIdx.x * 128, j0 = blockIdx.y * 128;

    float acc[2][8][4];
    #pragma unroll
    for (int mf = 0; mf < 2; mf++)
        #pragma unroll
        for (int nf = 0; nf < 8; nf++)
            #pragma unroll
            for (int e = 0; e < 4; e++) acc[mf][nf][e] = 0.0f;

    issue_proj(smu, m0, j0, 0, tid);                    CP_COMMIT();
    issue_proj(smu + PROJ_STRF * 4u, m0, j0, 64, tid);  CP_COMMIT();

    for (int ch = 0; ch < 16; ch++) {
        if (ch == 15) { CP_WAIT0(); } else { CP_WAIT1(); }
        __syncthreads();
        float* As = sm + (ch & 1) * PROJ_STRF;
        float* Ws = As + 8704;

        #pragma unroll
        for (int ks = 0; ks < 8; ks++) {
            int k0 = ks * 8;
            uint32_t a[2][4];
            #pragma unroll
            for (int mf = 0; mf < 2; mf++) {
                const float* ab = &As[(mw * 32 + mf * 16 + r) * 68 + k0 + c];
                a[mf][0] = __float_as_uint(ab[0]);
                a[mf][1] = __float_as_uint(ab[8 * 68]);
                a[mf][2] = __float_as_uint(ab[4]);
                a[mf][3] = __float_as_uint(ab[8 * 68 + 4]);
            }
            #pragma unroll
            for (int nf = 0; nf < 8; nf++) {
                const float* wb = &Ws[(nw * 64 + nf * 8 + r) * 68 + k0 + c];
                uint32_t b0 = __float_as_uint(wb[0]);
                uint32_t b1 = __float_as_uint(wb[4]);
                mma8(acc[0][nf], a[0][0], a[0][1], a[0][2], a[0][3], b0, b1);
                mma8(acc[1][nf], a[1][0], a[1][1], a[1][2], a[1][3], b0, b1);
            }
        }

        __syncthreads();
        if (ch + 2 < 16) {
            issue_proj(smu + (uint32_t)(ch & 1) * PROJ_STRF * 4u, m0, j0, (ch + 2) * 64, tid);
            CP_COMMIT();
        }
    }

    #pragma unroll
    for (int mf = 0; mf < 2; mf++) {
        int row = m0 + mw * 32 + mf * 16 + r;
        #pragma unroll
        for (int nf = 0; nf < 8; nf++) {
            int col = j0 + nw * 64 + nf * 8 + 2 * c;
            float2 bb = *(const float2*)&b_out[col];
            *(float2*)&out[(size_t)row * DIM + col] =
                make_float2(acc[mf][nf][0] + bb.x, acc[mf][nf][1] + bb.y);
            *(float2*)&out[(size_t)(row + 8) * DIM + col] =
                make_float2(acc[mf][nf][2] + bb.x, acc[mf][nf][3] + bb.y);
        }
    }
}

// ---------------------------------------------------------------------------
extern "C" void kernel_launch(void* const* d_in, const int* in_sizes, int n_in,
                              void* d_out, int out_size)
{
    const float* q        = (const float*)d_in[0];
    const float* k        = (const float*)d_in[1];
    const float* v        = (const float*)d_in[2];
    const float* qk_scale = (const float*)d_in[3];
    const float* w_out    = (const float*)d_in[4];
    const float* b_out    = (const float*)d_in[5];
    float* out = (float*)d_out;

    cudaFuncSetAttribute(attn_kernel,
                         cudaFuncAttributeMaxDynamicSharedMemorySize, ATTN_SMEM_BYTES);
    cudaFuncSetAttribute(proj_kernel,
                         cudaFuncAttributeMaxDynamicSharedMemorySize, PROJ_SMEM_BYTES);

    rope_table_kernel<<<(N_SEQ * 32 + 255) / 256, 256>>>();
    prep_qk_kernel<<<dim3(8192, 2), 256>>>(q, k, qk_scale);
    vround_kernel<<<(N_SEQ * DIM / 4) / 256, 256>>>(v);
    wround_kernel<<<(DIM * DIM / 4) / 256, 256>>>(w_out);
    attn_kernel<<<dim3(N_SEQ / 128, N_HEADS), 256, ATTN_SMEM_BYTES>>>();
    proj_kernel<<<dim3(N_SEQ / 128, DIM / 128), 256, PROJ_SMEM_BYTES>>>(b_out, out);
}